// round 1
// baseline (speedup 1.0000x reference)
#include <cuda_runtime.h>
#include <cuda_bf16.h>
#include <math.h>

#define NN 50000
#define HID 128
#define NG 512

// ---------------- scratch (static __device__, no runtime alloc) ----------------
__device__ float g_x[NN * HID];
__device__ float g_h[NN * HID];
__device__ float g_tmp[NN * HID];
__device__ float g_pool[NG * HID];
__device__ float g_EW[100 * HID];     // embed_tab @ W_comb[0:128]
__device__ float g_Wpc[4 * HID];      // rows 0..2: W_pos@W_comb[128:256]; row 3: fused bias

__device__ __forceinline__ float softplusf(float x) {
    return fmaxf(x, 0.f) + log1pf(expf(-fabsf(x)));
}

// ---------------- prep: fold the input-embedding algebra into tiny tables ------
__global__ void prep_kernel(const float* __restrict__ embed_tab,
                            const float* __restrict__ W_pos,
                            const float* __restrict__ b_pos,
                            const float* __restrict__ W_comb,
                            const float* __restrict__ b_comb) {
    int j = threadIdx.x;           // 0..127
    int b = blockIdx.x;            // 0..100
    if (b < 100) {
        float acc = 0.f;
        #pragma unroll 8
        for (int i = 0; i < HID; i++)
            acc += embed_tab[b * HID + i] * W_comb[i * HID + j];
        g_EW[b * HID + j] = acc;
    } else {
        float a0 = 0.f, a1 = 0.f, a2 = 0.f, ab = 0.f;
        #pragma unroll 8
        for (int i = 0; i < HID; i++) {
            float w = W_comb[(HID + i) * HID + j];
            a0 += W_pos[i] * w;
            a1 += W_pos[HID + i] * w;
            a2 += W_pos[2 * HID + i] * w;
            ab += b_pos[i] * w;
        }
        g_Wpc[j]           = a0;
        g_Wpc[HID + j]     = a1;
        g_Wpc[2 * HID + j] = a2;
        g_Wpc[3 * HID + j] = ab + b_comb[j];
    }
}

// ---------------- x0 = relu(EW[z] + pos@Wpc + bfuse); also seeds h ------------
__global__ void x0_kernel(const int* __restrict__ z, const float* __restrict__ pos, int N) {
    int tid = blockIdx.x * blockDim.x + threadIdx.x;
    int n = tid >> 5;
    if (n >= N) return;
    int c = tid & 31;
    int zz = __ldg(z + n);
    float p0 = __ldg(pos + n * 3), p1 = __ldg(pos + n * 3 + 1), p2 = __ldg(pos + n * 3 + 2);
    float4 ew = *(const float4*)(g_EW + zz * HID + c * 4);
    float4 w0 = *(const float4*)(g_Wpc + c * 4);
    float4 w1 = *(const float4*)(g_Wpc + HID + c * 4);
    float4 w2 = *(const float4*)(g_Wpc + 2 * HID + c * 4);
    float4 bf = *(const float4*)(g_Wpc + 3 * HID + c * 4);
    float4 v;
    v.x = fmaxf(ew.x + p0 * w0.x + p1 * w1.x + p2 * w2.x + bf.x, 0.f);
    v.y = fmaxf(ew.y + p0 * w0.y + p1 * w1.y + p2 * w2.y + bf.y, 0.f);
    v.z = fmaxf(ew.z + p0 * w0.z + p1 * w1.z + p2 * w2.z + bf.z, 0.f);
    v.w = fmaxf(ew.w + p0 * w0.w + p1 * w1.w + p2 * w2.w + bf.w, 0.f);
    *(float4*)(g_x + n * HID + c * 4) = v;
    *(float4*)(g_h + n * HID + c * 4) = v;   // seed h = x for aggregation
}

// ---------------- edge scatter: h[dst] += x[src] (h preseeded with x) ----------
__global__ void edge_kernel(const int* __restrict__ src, const int* __restrict__ dst, int E) {
    int tid = blockIdx.x * blockDim.x + threadIdx.x;
    int e = tid >> 5;
    if (e >= E) return;
    int c = tid & 31;
    int s = __ldg(src + e), d = __ldg(dst + e);
    float4 v = *(const float4*)(g_x + s * HID + c * 4);
    float* p = g_h + d * HID + c * 4;
    atomicAdd(p + 0, v.x);
    atomicAdd(p + 1, v.y);
    atomicAdd(p + 2, v.z);
    atomicAdd(p + 3, v.w);
}

// ---------------- fp32 GEMM: C[M,128] = act(A[M,128] @ B[128,128] + bias) -----
// 64-row x 128-col block tile, K=128 fully resident. Optional dual-write C2.
__global__ void gemm128(const float* __restrict__ A, const float* __restrict__ B,
                        const float* __restrict__ bias, float* __restrict__ C,
                        float* __restrict__ C2, int M, int do_relu) {
    extern __shared__ float sm[];
    float* Bs = sm;                // 128*128
    float* As = sm + HID * HID;    // 64*128
    int t = threadIdx.x;           // 256 threads
    float4* Bs4 = (float4*)Bs;
    const float4* B4 = (const float4*)B;
    #pragma unroll
    for (int i = 0; i < 16; i++) Bs4[t + i * 256] = B4[t + i * 256];

    int row0 = blockIdx.x * 64;
    int rows = min(64, M - row0);
    const float4* A4 = (const float4*)(A + (size_t)row0 * HID);
    float4* As4 = (float4*)As;
    #pragma unroll
    for (int i = 0; i < 8; i++) {
        int idx = t + i * 256;     // float4 index; row = idx/32
        if ((idx >> 5) < rows) As4[idx] = A4[idx];
    }
    __syncthreads();

    int tx = t & 31;               // col group: 4 consecutive floats
    int ty = t >> 5;               // row group: 8 rows
    float acc[8][4];
    float4 bb = ((const float4*)bias)[tx];
    #pragma unroll
    for (int i = 0; i < 8; i++) { acc[i][0] = bb.x; acc[i][1] = bb.y; acc[i][2] = bb.z; acc[i][3] = bb.w; }

    #pragma unroll 8
    for (int k = 0; k < HID; k++) {
        float4 b = Bs4[k * 32 + tx];
        #pragma unroll
        for (int i = 0; i < 8; i++) {
            float a = As[(ty * 8 + i) * HID + k];
            acc[i][0] += a * b.x;
            acc[i][1] += a * b.y;
            acc[i][2] += a * b.z;
            acc[i][3] += a * b.w;
        }
    }

    #pragma unroll
    for (int i = 0; i < 8; i++) {
        int row = row0 + ty * 8 + i;
        if (row < M) {
            float4 v;
            v.x = acc[i][0]; v.y = acc[i][1]; v.z = acc[i][2]; v.w = acc[i][3];
            if (do_relu) {
                v.x = fmaxf(v.x, 0.f); v.y = fmaxf(v.y, 0.f);
                v.z = fmaxf(v.z, 0.f); v.w = fmaxf(v.w, 0.f);
            }
            *(float4*)(C + (size_t)row * HID + tx * 4) = v;
            if (C2) *(float4*)(C2 + (size_t)row * HID + tx * 4) = v;
        }
    }
}

// ---------------- pooling ------------------------------------------------------
__global__ void zero_pool_kernel() {
    int tid = blockIdx.x * blockDim.x + threadIdx.x;
    if (tid < NG * HID) g_pool[tid] = 0.f;
}

__global__ void pool_kernel(const int* __restrict__ batch, int N) {
    int tid = blockIdx.x * blockDim.x + threadIdx.x;
    int n = tid >> 5;
    if (n >= N) return;
    int c = tid & 31;
    int gidx = __ldg(batch + n);
    float4 v = *(const float4*)(g_x + n * HID + c * 4);
    float* p = g_pool + gidx * HID + c * 4;
    atomicAdd(p + 0, v.x);
    atomicAdd(p + 1, v.y);
    atomicAdd(p + 2, v.z);
    atomicAdd(p + 3, v.w);
}

// ---------------- heads + evidential transforms -------------------------------
__global__ void heads_kernel(const float* __restrict__ W1, const float* __restrict__ b1,
                             const float* __restrict__ W2, const float* __restrict__ b2,
                             float* __restrict__ out) {
    __shared__ float sa[HID];
    __shared__ float red[HID];
    __shared__ float o[4];
    int g = blockIdx.x, j = threadIdx.x;
    sa[j] = g_pool[g * HID + j];
    __syncthreads();
    for (int k = 0; k < 4; k++) {
        float acc = b1[k * HID + j];
        const float* w = W1 + k * HID * HID + j;
        #pragma unroll 8
        for (int i = 0; i < HID; i++) acc += sa[i] * w[i * HID];
        acc = fmaxf(acc, 0.f);
        red[j] = acc * W2[k * HID + j];
        __syncthreads();
        for (int s = 64; s > 0; s >>= 1) {
            if (j < s) red[j] += red[j + s];
            __syncthreads();
        }
        if (j == 0) o[k] = red[0] + b2[k];
        __syncthreads();
    }
    if (j == 0) {
        float alpha = fmaxf(softplusf(o[0]) + 1.f, 1.f + 1e-4f);
        float beta  = softplusf(o[1]);
        float nu    = softplusf(o[2]);
        float gamma = o[3];
        float am1 = alpha - 1.f;
        out[g]            = gamma;
        out[NG + g]       = beta / am1;            // aleatoric
        out[2 * NG + g]   = beta / (am1 * nu);     // epistemic
        out[3 * NG + g]   = nu;
        out[4 * NG + g]   = alpha;
        out[5 * NG + g]   = beta;
    }
}

// ---------------- driver -------------------------------------------------------
extern "C" void kernel_launch(void* const* d_in, const int* in_sizes, int n_in,
                              void* d_out, int out_size) {
    const int*   z        = (const int*)d_in[0];
    const float* pos      = (const float*)d_in[1];
    const int*   batch    = (const int*)d_in[2];
    const int*   eidx     = (const int*)d_in[3];
    const float* embed    = (const float*)d_in[4];
    const float* W_pos    = (const float*)d_in[5];
    const float* b_pos    = (const float*)d_in[6];
    const float* W_comb   = (const float*)d_in[7];
    const float* b_comb   = (const float*)d_in[8];
    const float* gin_W1   = (const float*)d_in[9];
    const float* gin_b1   = (const float*)d_in[10];
    const float* gin_W2   = (const float*)d_in[11];
    const float* gin_b2   = (const float*)d_in[12];
    const float* head_W1  = (const float*)d_in[13];
    const float* head_b1  = (const float*)d_in[14];
    const float* head_W2  = (const float*)d_in[15];
    const float* head_b2  = (const float*)d_in[16];
    float* out = (float*)d_out;

    const int N = in_sizes[0];
    const int E = in_sizes[3] / 2;
    const int* src = eidx;
    const int* dst = eidx + E;

    const int smem_gemm = (HID * HID + 64 * HID) * sizeof(float);   // 96 KB
    cudaFuncSetAttribute(gemm128, cudaFuncAttributeMaxDynamicSharedMemorySize, smem_gemm);

    float *x, *h, *tmp;
    cudaGetSymbolAddress((void**)&x, g_x);
    cudaGetSymbolAddress((void**)&h, g_h);
    cudaGetSymbolAddress((void**)&tmp, g_tmp);

    // 1. fold input embedding weights
    prep_kernel<<<101, 128>>>(embed, W_pos, b_pos, W_comb, b_comb);

    // 2. x0 (also seeds h)
    {
        int threads = N * 32;
        x0_kernel<<<(threads + 255) / 256, 256>>>(z, pos, N);
    }

    // 3. GIN layers
    const int gemm_blocks = (N + 63) / 64;
    for (int l = 0; l < 4; l++) {
        int ethreads = E * 32;
        edge_kernel<<<(ethreads + 255) / 256, 256>>>(src, dst, E);
        gemm128<<<gemm_blocks, 256, smem_gemm>>>(h, gin_W1 + l * HID * HID,
                                                 gin_b1 + l * HID, tmp, nullptr, N, 1);
        // second GEMM writes x; dual-write seeds h for the next layer's aggregation
        float* c2 = (l < 3) ? h : nullptr;
        int relu = (l < 3) ? 1 : 0;
        gemm128<<<gemm_blocks, 256, smem_gemm>>>(tmp, gin_W2 + l * HID * HID,
                                                 gin_b2 + l * HID, x, c2, N, relu);
    }

    // 4. pool per graph
    zero_pool_kernel<<<(NG * HID + 255) / 256, 256>>>();
    {
        int threads = N * 32;
        pool_kernel<<<(threads + 255) / 256, 256>>>(batch, N);
    }

    // 5. heads
    heads_kernel<<<NG, 128>>>(head_W1, head_b1, head_W2, head_b2, out);
}

// round 2
// speedup vs baseline: 1.6666x; 1.6666x over previous
#include <cuda_runtime.h>
#include <cuda_bf16.h>
#include <math.h>

#define NN 50000
#define HID 128
#define NG 512

// ---------------- scratch (static __device__, no runtime alloc) ----------------
__device__ float g_x[NN * HID];
__device__ float g_h[NN * HID];
__device__ float g_tmp[NN * HID];
__device__ float g_pool[NG * HID];
__device__ float g_EW[100 * HID];     // embed_tab @ W_comb[0:128]
__device__ float g_Wpc[4 * HID];      // rows 0..2: W_pos@W_comb[128:256]; row 3: fused bias

__device__ __forceinline__ float softplusf(float x) {
    return fmaxf(x, 0.f) + log1pf(expf(-fabsf(x)));
}

__device__ __forceinline__ void red_add_v4(float* p, float4 v) {
    asm volatile("red.global.add.v4.f32 [%0], {%1, %2, %3, %4};"
                 :: "l"(p), "f"(v.x), "f"(v.y), "f"(v.z), "f"(v.w) : "memory");
}

// ---------------- prep: fold the input-embedding algebra into tiny tables ------
__global__ void prep_kernel(const float* __restrict__ embed_tab,
                            const float* __restrict__ W_pos,
                            const float* __restrict__ b_pos,
                            const float* __restrict__ W_comb,
                            const float* __restrict__ b_comb) {
    int j = threadIdx.x;           // 0..127
    int b = blockIdx.x;            // 0..100
    if (b < 100) {
        float acc = 0.f;
        #pragma unroll 8
        for (int i = 0; i < HID; i++)
            acc += embed_tab[b * HID + i] * W_comb[i * HID + j];
        g_EW[b * HID + j] = acc;
    } else {
        float a0 = 0.f, a1 = 0.f, a2 = 0.f, ab = 0.f;
        #pragma unroll 8
        for (int i = 0; i < HID; i++) {
            float w = W_comb[(HID + i) * HID + j];
            a0 += W_pos[i] * w;
            a1 += W_pos[HID + i] * w;
            a2 += W_pos[2 * HID + i] * w;
            ab += b_pos[i] * w;
        }
        g_Wpc[j]           = a0;
        g_Wpc[HID + j]     = a1;
        g_Wpc[2 * HID + j] = a2;
        g_Wpc[3 * HID + j] = ab + b_comb[j];
    }
}

// ---------------- x0 = relu(EW[z] + pos@Wpc + bfuse); also seeds h ------------
__global__ void x0_kernel(const int* __restrict__ z, const float* __restrict__ pos, int N) {
    int tid = blockIdx.x * blockDim.x + threadIdx.x;
    int n = tid >> 5;
    if (n >= N) return;
    int c = tid & 31;
    int zz = __ldg(z + n);
    float p0 = __ldg(pos + n * 3), p1 = __ldg(pos + n * 3 + 1), p2 = __ldg(pos + n * 3 + 2);
    float4 ew = *(const float4*)(g_EW + zz * HID + c * 4);
    float4 w0 = *(const float4*)(g_Wpc + c * 4);
    float4 w1 = *(const float4*)(g_Wpc + HID + c * 4);
    float4 w2 = *(const float4*)(g_Wpc + 2 * HID + c * 4);
    float4 bf = *(const float4*)(g_Wpc + 3 * HID + c * 4);
    float4 v;
    v.x = fmaxf(ew.x + p0 * w0.x + p1 * w1.x + p2 * w2.x + bf.x, 0.f);
    v.y = fmaxf(ew.y + p0 * w0.y + p1 * w1.y + p2 * w2.y + bf.y, 0.f);
    v.z = fmaxf(ew.z + p0 * w0.z + p1 * w1.z + p2 * w2.z + bf.z, 0.f);
    v.w = fmaxf(ew.w + p0 * w0.w + p1 * w1.w + p2 * w2.w + bf.w, 0.f);
    *(float4*)(g_x + n * HID + c * 4) = v;
    *(float4*)(g_h + n * HID + c * 4) = v;   // seed h = x for aggregation
}

// ---------------- edge scatter: h[dst] += x[src] (h preseeded with x) ----------
__global__ void edge_kernel(const int* __restrict__ src, const int* __restrict__ dst, int E) {
    int tid = blockIdx.x * blockDim.x + threadIdx.x;
    int e = tid >> 5;
    if (e >= E) return;
    int c = tid & 31;
    int s = __ldg(src + e), d = __ldg(dst + e);
    float4 v = *(const float4*)(g_x + s * HID + c * 4);
    red_add_v4(g_h + d * HID + c * 4, v);
}

// ---------------- fp32 GEMM: C[M,128] = act(A[M,128] @ B[128,128] + bias) -----
// 64-row x 128-col block tile, 128 threads, 16x4 register tile per thread.
// Warp = one row-group (ty) -> A loads are pure smem broadcasts.
// Optional dual-write C2 and fused sum-pool (red.v4 into g_pool via batch).
__global__ __launch_bounds__(128, 2)
void gemm128(const float* __restrict__ A, const float* __restrict__ B,
             const float* __restrict__ bias, float* __restrict__ C,
             float* __restrict__ C2, const int* __restrict__ batch,
             int M, int do_relu) {
    __shared__ float4 Bs[HID * 32];   // [k][col4]  64 KB
    __shared__ float4 As[64 * 32];    // [row][k4]  32 KB
    int t = threadIdx.x;              // 128 threads

    const float4* B4 = (const float4*)B;
    #pragma unroll
    for (int i = 0; i < 32; i++) Bs[t + i * 128] = B4[t + i * 128];

    int row0 = blockIdx.x * 64;
    const float4* A4 = (const float4*)(A + (size_t)row0 * HID);
    #pragma unroll
    for (int i = 0; i < 16; i++) {
        int idx = t + i * 128;        // f4 index; row = idx>>5
        if (row0 + (idx >> 5) < M) As[idx] = A4[idx];
    }
    __syncthreads();

    int tx = t & 31;                  // col4 index (4 floats)
    int ty = t >> 5;                  // row group: rows ty*16 .. ty*16+15
    float4 acc[16];
    float4 bb = ((const float4*)bias)[tx];
    #pragma unroll
    for (int i = 0; i < 16; i++) acc[i] = bb;

    #pragma unroll 2
    for (int k4 = 0; k4 < 32; k4++) {
        float4 b0 = Bs[(k4 * 4 + 0) * 32 + tx];
        float4 b1 = Bs[(k4 * 4 + 1) * 32 + tx];
        float4 b2 = Bs[(k4 * 4 + 2) * 32 + tx];
        float4 b3 = Bs[(k4 * 4 + 3) * 32 + tx];
        #pragma unroll
        for (int i = 0; i < 16; i++) {
            float4 a = As[(ty * 16 + i) * 32 + k4];   // broadcast across warp
            acc[i].x += a.x * b0.x; acc[i].y += a.x * b0.y; acc[i].z += a.x * b0.z; acc[i].w += a.x * b0.w;
            acc[i].x += a.y * b1.x; acc[i].y += a.y * b1.y; acc[i].z += a.y * b1.z; acc[i].w += a.y * b1.w;
            acc[i].x += a.z * b2.x; acc[i].y += a.z * b2.y; acc[i].z += a.z * b2.z; acc[i].w += a.z * b2.w;
            acc[i].x += a.w * b3.x; acc[i].y += a.w * b3.y; acc[i].z += a.w * b3.z; acc[i].w += a.w * b3.w;
        }
    }

    float4* C4 = (float4*)C;
    float4* C24 = (float4*)C2;
    #pragma unroll
    for (int i = 0; i < 16; i++) {
        int row = row0 + ty * 16 + i;
        if (row < M) {
            float4 v = acc[i];
            if (do_relu) {
                v.x = fmaxf(v.x, 0.f); v.y = fmaxf(v.y, 0.f);
                v.z = fmaxf(v.z, 0.f); v.w = fmaxf(v.w, 0.f);
            }
            C4[(size_t)row * 32 + tx] = v;
            if (C2) C24[(size_t)row * 32 + tx] = v;
            if (batch) {
                int gidx = __ldg(batch + row);
                red_add_v4(g_pool + gidx * HID + tx * 4, v);
            }
        }
    }
}

// ---------------- pooling prep -------------------------------------------------
__global__ void zero_pool_kernel() {
    int tid = blockIdx.x * blockDim.x + threadIdx.x;
    if (tid < NG * HID) g_pool[tid] = 0.f;
}

// ---------------- heads + evidential transforms -------------------------------
__global__ void heads_kernel(const float* __restrict__ W1, const float* __restrict__ b1,
                             const float* __restrict__ W2, const float* __restrict__ b2,
                             float* __restrict__ out) {
    __shared__ float sa[HID];
    __shared__ float red[HID];
    __shared__ float o[4];
    int g = blockIdx.x, j = threadIdx.x;
    sa[j] = g_pool[g * HID + j];
    __syncthreads();
    for (int k = 0; k < 4; k++) {
        float acc = b1[k * HID + j];
        const float* w = W1 + k * HID * HID + j;
        #pragma unroll 8
        for (int i = 0; i < HID; i++) acc += sa[i] * w[i * HID];
        acc = fmaxf(acc, 0.f);
        red[j] = acc * W2[k * HID + j];
        __syncthreads();
        for (int s = 64; s > 0; s >>= 1) {
            if (j < s) red[j] += red[j + s];
            __syncthreads();
        }
        if (j == 0) o[k] = red[0] + b2[k];
        __syncthreads();
    }
    if (j == 0) {
        float alpha = fmaxf(softplusf(o[0]) + 1.f, 1.f + 1e-4f);
        float beta  = softplusf(o[1]);
        float nu    = softplusf(o[2]);
        float gamma = o[3];
        float am1 = alpha - 1.f;
        out[g]            = gamma;
        out[NG + g]       = beta / am1;            // aleatoric
        out[2 * NG + g]   = beta / (am1 * nu);     // epistemic
        out[3 * NG + g]   = nu;
        out[4 * NG + g]   = alpha;
        out[5 * NG + g]   = beta;
    }
}

// ---------------- driver -------------------------------------------------------
extern "C" void kernel_launch(void* const* d_in, const int* in_sizes, int n_in,
                              void* d_out, int out_size) {
    const int*   z        = (const int*)d_in[0];
    const float* pos      = (const float*)d_in[1];
    const int*   batch    = (const int*)d_in[2];
    const int*   eidx     = (const int*)d_in[3];
    const float* embed    = (const float*)d_in[4];
    const float* W_pos    = (const float*)d_in[5];
    const float* b_pos    = (const float*)d_in[6];
    const float* W_comb   = (const float*)d_in[7];
    const float* b_comb   = (const float*)d_in[8];
    const float* gin_W1   = (const float*)d_in[9];
    const float* gin_b1   = (const float*)d_in[10];
    const float* gin_W2   = (const float*)d_in[11];
    const float* gin_b2   = (const float*)d_in[12];
    const float* head_W1  = (const float*)d_in[13];
    const float* head_b1  = (const float*)d_in[14];
    const float* head_W2  = (const float*)d_in[15];
    const float* head_b2  = (const float*)d_in[16];
    float* out = (float*)d_out;

    const int N = in_sizes[0];
    const int E = in_sizes[3] / 2;
    const int* src = eidx;
    const int* dst = eidx + E;

    float *x, *h, *tmp;
    cudaGetSymbolAddress((void**)&x, g_x);
    cudaGetSymbolAddress((void**)&h, g_h);
    cudaGetSymbolAddress((void**)&tmp, g_tmp);

    // 1. fold input embedding weights; zero the pool buffer (used in layer 3)
    prep_kernel<<<101, 128>>>(embed, W_pos, b_pos, W_comb, b_comb);
    zero_pool_kernel<<<(NG * HID + 255) / 256, 256>>>();

    // 2. x0 (also seeds h)
    {
        int threads = N * 32;
        x0_kernel<<<(threads + 255) / 256, 256>>>(z, pos, N);
    }

    // 3. GIN layers
    const int gemm_blocks = (N + 63) / 64;
    for (int l = 0; l < 4; l++) {
        int ethreads = E * 32;
        edge_kernel<<<(ethreads + 255) / 256, 256>>>(src, dst, E);
        gemm128<<<gemm_blocks, 128>>>(h, gin_W1 + l * HID * HID,
                                      gin_b1 + l * HID, tmp, nullptr, nullptr, N, 1);
        // second GEMM writes x; dual-write seeds h for the next layer's aggregation;
        // last layer fuses the per-graph sum pooling into the epilogue
        float* c2 = (l < 3) ? h : nullptr;
        const int* bptr = (l == 3) ? batch : nullptr;
        int relu = (l < 3) ? 1 : 0;
        gemm128<<<gemm_blocks, 128>>>(tmp, gin_W2 + l * HID * HID,
                                      gin_b2 + l * HID, x, c2, bptr, N, relu);
    }

    // 4. heads
    heads_kernel<<<NG, 128>>>(head_W1, head_b1, head_W2, head_b2, out);
}

// round 3
// speedup vs baseline: 1.9938x; 1.1963x over previous
#include <cuda_runtime.h>
#include <cuda_bf16.h>
#include <math.h>

#define NN 50000
#define NE_MAX 800000
#define HID 128
#define NG 512

// ---------------- scratch (static __device__, no runtime alloc) ----------------
__device__ float g_x[NN * HID];
__device__ float g_h[NN * HID];
__device__ float g_tmp[NN * HID];
__device__ float g_pool[NG * HID];
__device__ float g_EW[100 * HID];     // embed_tab @ W_comb[0:128]
__device__ float g_Wpc[4 * HID];      // rows 0..2: W_pos@W_comb[128:256]; row 3: fused bias
__device__ int   g_deg[NN];
__device__ int   g_off[NN + 1];
__device__ int   g_cur[NN];
__device__ int   g_srcs[NE_MAX];      // dst-sorted src indices (CSR)

__device__ __forceinline__ float softplusf(float x) {
    return fmaxf(x, 0.f) + log1pf(expf(-fabsf(x)));
}

__device__ __forceinline__ void red_add_v4(float* p, float4 v) {
    asm volatile("red.global.add.v4.f32 [%0], {%1, %2, %3, %4};"
                 :: "l"(p), "f"(v.x), "f"(v.y), "f"(v.z), "f"(v.w) : "memory");
}

// ================= CSR build (once per call, reused across 4 layers) ===========
__global__ void zero_deg_kernel() {
    int i = blockIdx.x * blockDim.x + threadIdx.x;
    if (i < NN) g_deg[i] = 0;
}

__global__ void hist_kernel(const int* __restrict__ dst, int E) {
    int e = blockIdx.x * blockDim.x + threadIdx.x;
    if (e < E) atomicAdd(&g_deg[__ldg(dst + e)], 1);
}

__global__ void scan_kernel() {   // single block, 1024 threads
    __shared__ int part[1024];
    int t = threadIdx.x;
    const int CH = (NN + 1023) / 1024;
    int base = t * CH;
    int s = 0;
    for (int i = 0; i < CH; i++) {
        int idx = base + i;
        if (idx < NN) s += g_deg[idx];
    }
    part[t] = s;
    __syncthreads();
    for (int off = 1; off < 1024; off <<= 1) {
        int v = (t >= off) ? part[t - off] : 0;
        __syncthreads();
        part[t] += v;
        __syncthreads();
    }
    int run = (t == 0) ? 0 : part[t - 1];
    for (int i = 0; i < CH; i++) {
        int idx = base + i;
        if (idx < NN) {
            g_off[idx] = run;
            g_cur[idx] = run;
            run += g_deg[idx];
        }
    }
    if (t == 1023) g_off[NN] = run;
}

__global__ void fill_kernel(const int* __restrict__ src, const int* __restrict__ dst, int E) {
    int e = blockIdx.x * blockDim.x + threadIdx.x;
    if (e >= E) return;
    int d = __ldg(dst + e);
    int p = atomicAdd(&g_cur[d], 1);
    g_srcs[p] = __ldg(src + e);
}

// ---------------- prep: fold the input-embedding algebra into tiny tables ------
__global__ void prep_kernel(const float* __restrict__ embed_tab,
                            const float* __restrict__ W_pos,
                            const float* __restrict__ b_pos,
                            const float* __restrict__ W_comb,
                            const float* __restrict__ b_comb) {
    int j = threadIdx.x;           // 0..127
    int b = blockIdx.x;            // 0..100
    if (b < 100) {
        float acc = 0.f;
        #pragma unroll 8
        for (int i = 0; i < HID; i++)
            acc += embed_tab[b * HID + i] * W_comb[i * HID + j];
        g_EW[b * HID + j] = acc;
    } else {
        float a0 = 0.f, a1 = 0.f, a2 = 0.f, ab = 0.f;
        #pragma unroll 8
        for (int i = 0; i < HID; i++) {
            float w = W_comb[(HID + i) * HID + j];
            a0 += W_pos[i] * w;
            a1 += W_pos[HID + i] * w;
            a2 += W_pos[2 * HID + i] * w;
            ab += b_pos[i] * w;
        }
        g_Wpc[j]           = a0;
        g_Wpc[HID + j]     = a1;
        g_Wpc[2 * HID + j] = a2;
        g_Wpc[3 * HID + j] = ab + b_comb[j];
    }
}

// ---------------- x0 = relu(EW[z] + pos@Wpc + bfuse) ---------------------------
__global__ void x0_kernel(const int* __restrict__ z, const float* __restrict__ pos, int N) {
    int tid = blockIdx.x * blockDim.x + threadIdx.x;
    int n = tid >> 5;
    if (n >= N) return;
    int c = tid & 31;
    int zz = __ldg(z + n);
    float p0 = __ldg(pos + n * 3), p1 = __ldg(pos + n * 3 + 1), p2 = __ldg(pos + n * 3 + 2);
    float4 ew = *(const float4*)(g_EW + zz * HID + c * 4);
    float4 w0 = *(const float4*)(g_Wpc + c * 4);
    float4 w1 = *(const float4*)(g_Wpc + HID + c * 4);
    float4 w2 = *(const float4*)(g_Wpc + 2 * HID + c * 4);
    float4 bf = *(const float4*)(g_Wpc + 3 * HID + c * 4);
    float4 v;
    v.x = fmaxf(ew.x + p0 * w0.x + p1 * w1.x + p2 * w2.x + bf.x, 0.f);
    v.y = fmaxf(ew.y + p0 * w0.y + p1 * w1.y + p2 * w2.y + bf.y, 0.f);
    v.z = fmaxf(ew.z + p0 * w0.z + p1 * w1.z + p2 * w2.z + bf.z, 0.f);
    v.w = fmaxf(ew.w + p0 * w0.w + p1 * w1.w + p2 * w2.w + bf.w, 0.f);
    *(float4*)(g_x + n * HID + c * 4) = v;
}

// ---------------- CSR aggregation: h[n] = x[n] + sum_{e in N(n)} x[src[e]] -----
// One warp per node; lane owns 4 consecutive floats. 4-way edge unroll for MLP.
__global__ void agg_kernel(int N) {
    int tid = blockIdx.x * blockDim.x + threadIdx.x;
    int n = tid >> 5;
    if (n >= N) return;
    int lane = tid & 31;
    const float4* x4 = (const float4*)g_x;
    float4 a0 = x4[n * 32 + lane];
    float4 a1 = {0.f, 0.f, 0.f, 0.f};
    float4 a2 = {0.f, 0.f, 0.f, 0.f};
    float4 a3 = {0.f, 0.f, 0.f, 0.f};
    int beg = __ldg(&g_off[n]), end = __ldg(&g_off[n + 1]);
    int e = beg;
    for (; e + 4 <= end; e += 4) {
        int s0 = __ldg(&g_srcs[e]);
        int s1 = __ldg(&g_srcs[e + 1]);
        int s2 = __ldg(&g_srcs[e + 2]);
        int s3 = __ldg(&g_srcs[e + 3]);
        float4 v0 = x4[s0 * 32 + lane];
        float4 v1 = x4[s1 * 32 + lane];
        float4 v2 = x4[s2 * 32 + lane];
        float4 v3 = x4[s3 * 32 + lane];
        a0.x += v0.x; a0.y += v0.y; a0.z += v0.z; a0.w += v0.w;
        a1.x += v1.x; a1.y += v1.y; a1.z += v1.z; a1.w += v1.w;
        a2.x += v2.x; a2.y += v2.y; a2.z += v2.z; a2.w += v2.w;
        a3.x += v3.x; a3.y += v3.y; a3.z += v3.z; a3.w += v3.w;
    }
    for (; e < end; e++) {
        int s = __ldg(&g_srcs[e]);
        float4 v = x4[s * 32 + lane];
        a0.x += v.x; a0.y += v.y; a0.z += v.z; a0.w += v.w;
    }
    float4 r;
    r.x = a0.x + a1.x + a2.x + a3.x;
    r.y = a0.y + a1.y + a2.y + a3.y;
    r.z = a0.z + a1.z + a2.z + a3.z;
    r.w = a0.w + a1.w + a2.w + a3.w;
    ((float4*)g_h)[n * 32 + lane] = r;
}

// ---------------- fp32 GEMM: C[M,128] = act(A[M,128] @ B[128,128] + bias) -----
// 64-row x 128-col block tile, 128 threads, 16x4 register tile per thread.
// Warp = one row-group (ty) -> A loads are pure smem broadcasts.
// Optional fused sum-pool (red.v4 into g_pool via batch).
__global__ __launch_bounds__(128, 2)
void gemm128(const float* __restrict__ A, const float* __restrict__ B,
             const float* __restrict__ bias, float* __restrict__ C,
             const int* __restrict__ batch, int M, int do_relu) {
    __shared__ float4 Bs[HID * 32];   // [k][col4]  64 KB
    __shared__ float4 As[64 * 32];    // [row][k4]  32 KB
    int t = threadIdx.x;              // 128 threads

    const float4* B4 = (const float4*)B;
    #pragma unroll
    for (int i = 0; i < 32; i++) Bs[t + i * 128] = B4[t + i * 128];

    int row0 = blockIdx.x * 64;
    const float4* A4 = (const float4*)(A + (size_t)row0 * HID);
    #pragma unroll
    for (int i = 0; i < 16; i++) {
        int idx = t + i * 128;        // f4 index; row = idx>>5
        if (row0 + (idx >> 5) < M) As[idx] = A4[idx];
    }
    __syncthreads();

    int tx = t & 31;                  // col4 index (4 floats)
    int ty = t >> 5;                  // row group: rows ty*16 .. ty*16+15
    float4 acc[16];
    float4 bb = ((const float4*)bias)[tx];
    #pragma unroll
    for (int i = 0; i < 16; i++) acc[i] = bb;

    #pragma unroll 2
    for (int k4 = 0; k4 < 32; k4++) {
        float4 b0 = Bs[(k4 * 4 + 0) * 32 + tx];
        float4 b1 = Bs[(k4 * 4 + 1) * 32 + tx];
        float4 b2 = Bs[(k4 * 4 + 2) * 32 + tx];
        float4 b3 = Bs[(k4 * 4 + 3) * 32 + tx];
        #pragma unroll
        for (int i = 0; i < 16; i++) {
            float4 a = As[(ty * 16 + i) * 32 + k4];   // broadcast across warp
            acc[i].x += a.x * b0.x; acc[i].y += a.x * b0.y; acc[i].z += a.x * b0.z; acc[i].w += a.x * b0.w;
            acc[i].x += a.y * b1.x; acc[i].y += a.y * b1.y; acc[i].z += a.y * b1.z; acc[i].w += a.y * b1.w;
            acc[i].x += a.z * b2.x; acc[i].y += a.z * b2.y; acc[i].z += a.z * b2.z; acc[i].w += a.z * b2.w;
            acc[i].x += a.w * b3.x; acc[i].y += a.w * b3.y; acc[i].z += a.w * b3.z; acc[i].w += a.w * b3.w;
        }
    }

    float4* C4 = (float4*)C;
    #pragma unroll
    for (int i = 0; i < 16; i++) {
        int row = row0 + ty * 16 + i;
        if (row < M) {
            float4 v = acc[i];
            if (do_relu) {
                v.x = fmaxf(v.x, 0.f); v.y = fmaxf(v.y, 0.f);
                v.z = fmaxf(v.z, 0.f); v.w = fmaxf(v.w, 0.f);
            }
            C4[(size_t)row * 32 + tx] = v;
            if (batch) {
                int gidx = __ldg(batch + row);
                red_add_v4(g_pool + gidx * HID + tx * 4, v);
            }
        }
    }
}

// ---------------- pooling prep -------------------------------------------------
__global__ void zero_pool_kernel() {
    int tid = blockIdx.x * blockDim.x + threadIdx.x;
    if (tid < NG * HID) g_pool[tid] = 0.f;
}

// ---------------- heads + evidential transforms -------------------------------
__global__ void heads_kernel(const float* __restrict__ W1, const float* __restrict__ b1,
                             const float* __restrict__ W2, const float* __restrict__ b2,
                             float* __restrict__ out) {
    __shared__ float sa[HID];
    __shared__ float red[HID];
    __shared__ float o[4];
    int g = blockIdx.x, j = threadIdx.x;
    sa[j] = g_pool[g * HID + j];
    __syncthreads();
    for (int k = 0; k < 4; k++) {
        float acc = b1[k * HID + j];
        const float* w = W1 + k * HID * HID + j;
        #pragma unroll 8
        for (int i = 0; i < HID; i++) acc += sa[i] * w[i * HID];
        acc = fmaxf(acc, 0.f);
        red[j] = acc * W2[k * HID + j];
        __syncthreads();
        for (int s = 64; s > 0; s >>= 1) {
            if (j < s) red[j] += red[j + s];
            __syncthreads();
        }
        if (j == 0) o[k] = red[0] + b2[k];
        __syncthreads();
    }
    if (j == 0) {
        float alpha = fmaxf(softplusf(o[0]) + 1.f, 1.f + 1e-4f);
        float beta  = softplusf(o[1]);
        float nu    = softplusf(o[2]);
        float gamma = o[3];
        float am1 = alpha - 1.f;
        out[g]            = gamma;
        out[NG + g]       = beta / am1;            // aleatoric
        out[2 * NG + g]   = beta / (am1 * nu);     // epistemic
        out[3 * NG + g]   = nu;
        out[4 * NG + g]   = alpha;
        out[5 * NG + g]   = beta;
    }
}

// ---------------- driver -------------------------------------------------------
extern "C" void kernel_launch(void* const* d_in, const int* in_sizes, int n_in,
                              void* d_out, int out_size) {
    const int*   z        = (const int*)d_in[0];
    const float* pos      = (const float*)d_in[1];
    const int*   batch    = (const int*)d_in[2];
    const int*   eidx     = (const int*)d_in[3];
    const float* embed    = (const float*)d_in[4];
    const float* W_pos    = (const float*)d_in[5];
    const float* b_pos    = (const float*)d_in[6];
    const float* W_comb   = (const float*)d_in[7];
    const float* b_comb   = (const float*)d_in[8];
    const float* gin_W1   = (const float*)d_in[9];
    const float* gin_b1   = (const float*)d_in[10];
    const float* gin_W2   = (const float*)d_in[11];
    const float* gin_b2   = (const float*)d_in[12];
    const float* head_W1  = (const float*)d_in[13];
    const float* head_b1  = (const float*)d_in[14];
    const float* head_W2  = (const float*)d_in[15];
    const float* head_b2  = (const float*)d_in[16];
    float* out = (float*)d_out;

    const int N = in_sizes[0];
    const int E = in_sizes[3] / 2;
    const int* src = eidx;
    const int* dst = eidx + E;

    float *x, *h, *tmp;
    cudaGetSymbolAddress((void**)&x, g_x);
    cudaGetSymbolAddress((void**)&h, g_h);
    cudaGetSymbolAddress((void**)&tmp, g_tmp);

    // 1. CSR build (amortized over 4 layers) + weight folding + pool zero
    zero_deg_kernel<<<(NN + 255) / 256, 256>>>();
    hist_kernel<<<(E + 255) / 256, 256>>>(dst, E);
    scan_kernel<<<1, 1024>>>();
    fill_kernel<<<(E + 255) / 256, 256>>>(src, dst, E);
    prep_kernel<<<101, 128>>>(embed, W_pos, b_pos, W_comb, b_comb);
    zero_pool_kernel<<<(NG * HID + 255) / 256, 256>>>();

    // 2. x0
    {
        int threads = N * 32;
        x0_kernel<<<(threads + 255) / 256, 256>>>(z, pos, N);
    }

    // 3. GIN layers
    const int gemm_blocks = (N + 63) / 64;
    const int agg_blocks = (N * 32 + 255) / 256;
    for (int l = 0; l < 4; l++) {
        agg_kernel<<<agg_blocks, 256>>>(N);
        gemm128<<<gemm_blocks, 128>>>(h, gin_W1 + l * HID * HID,
                                      gin_b1 + l * HID, tmp, nullptr, N, 1);
        // second GEMM writes x; last layer fuses per-graph sum pooling
        const int* bptr = (l == 3) ? batch : nullptr;
        int relu = (l < 3) ? 1 : 0;
        gemm128<<<gemm_blocks, 128>>>(tmp, gin_W2 + l * HID * HID,
                                      gin_b2 + l * HID, x, bptr, N, relu);
    }

    // 4. heads
    heads_kernel<<<NG, 128>>>(head_W1, head_b1, head_W2, head_b2, out);
}

// round 5
// speedup vs baseline: 2.4861x; 1.2469x over previous
#include <cuda_runtime.h>
#include <cuda_bf16.h>
#include <math.h>
#include <stdint.h>

#define NN 50000
#define NE_MAX 800000
#define HID 128
#define NG 512

// ---------------- scratch (static __device__, no runtime alloc) ----------------
__device__ float g_x[NN * HID];
__device__ float g_h[NN * HID];
__device__ float g_tmp[NN * HID];
__device__ float g_pool[NG * HID];
__device__ float g_EW[100 * HID];
__device__ float g_Wpc[4 * HID];
__device__ int   g_deg[NN];
__device__ int   g_off[NN + 1];
__device__ int   g_cur[NN];
__device__ int   g_srcs[NE_MAX];
// bf16 hi/lo split, TRANSPOSED weights: Bt[n*HID+k] = W[k*HID+n]; 8 matrices
__device__ __nv_bfloat16 g_whi[8 * HID * HID];
__device__ __nv_bfloat16 g_wlo[8 * HID * HID];

__device__ __forceinline__ float softplusf(float x) {
    return fmaxf(x, 0.f) + log1pf(expf(-fabsf(x)));
}

__device__ __forceinline__ void red_add_v2(float* p, float a, float b) {
    asm volatile("red.global.add.v2.f32 [%0], {%1, %2};"
                 :: "l"(p), "f"(a), "f"(b) : "memory");
}

__device__ __forceinline__ uint32_t smem_u32(const void* p) {
    uint32_t a;
    asm("{ .reg .u64 t; cvta.to.shared.u64 t, %1; cvt.u32.u64 %0, t; }" : "=r"(a) : "l"(p));
    return a;
}

#define LDSM_X4(r0, r1, r2, r3, addr) \
    asm volatile("ldmatrix.sync.aligned.m8n8.x4.shared.b16 {%0,%1,%2,%3}, [%4];" \
                 : "=r"(r0), "=r"(r1), "=r"(r2), "=r"(r3) : "r"(addr))

#define MMA16816(c, a, b0, b1) \
    asm volatile("mma.sync.aligned.m16n8k16.row.col.f32.bf16.bf16.f32 " \
                 "{%0,%1,%2,%3}, {%4,%5,%6,%7}, {%8,%9}, {%0,%1,%2,%3};" \
                 : "+f"((c)[0]), "+f"((c)[1]), "+f"((c)[2]), "+f"((c)[3]) \
                 : "r"((a)[0]), "r"((a)[1]), "r"((a)[2]), "r"((a)[3]), "r"(b0), "r"(b1))

// ================= CSR build ====================================================
__global__ void zero_deg_kernel() {
    int i = blockIdx.x * blockDim.x + threadIdx.x;
    if (i < NN) g_deg[i] = 0;
}
__global__ void hist_kernel(const int* __restrict__ dst, int E) {
    int e = blockIdx.x * blockDim.x + threadIdx.x;
    if (e < E) atomicAdd(&g_deg[__ldg(dst + e)], 1);
}
__global__ void scan_kernel() {
    __shared__ int part[1024];
    int t = threadIdx.x;
    const int CH = (NN + 1023) / 1024;
    int base = t * CH;
    int s = 0;
    for (int i = 0; i < CH; i++) { int idx = base + i; if (idx < NN) s += g_deg[idx]; }
    part[t] = s;
    __syncthreads();
    for (int off = 1; off < 1024; off <<= 1) {
        int v = (t >= off) ? part[t - off] : 0;
        __syncthreads();
        part[t] += v;
        __syncthreads();
    }
    int run = (t == 0) ? 0 : part[t - 1];
    for (int i = 0; i < CH; i++) {
        int idx = base + i;
        if (idx < NN) { g_off[idx] = run; g_cur[idx] = run; run += g_deg[idx]; }
    }
    if (t == 1023) g_off[NN] = run;
}
__global__ void fill_kernel(const int* __restrict__ src, const int* __restrict__ dst, int E) {
    int e = blockIdx.x * blockDim.x + threadIdx.x;
    if (e >= E) return;
    int d = __ldg(dst + e);
    int p = atomicAdd(&g_cur[d], 1);
    g_srcs[p] = __ldg(src + e);
}

// ---------------- prep: fold input-embedding algebra ---------------------------
__global__ void prep_kernel(const float* __restrict__ embed_tab,
                            const float* __restrict__ W_pos,
                            const float* __restrict__ b_pos,
                            const float* __restrict__ W_comb,
                            const float* __restrict__ b_comb) {
    int j = threadIdx.x;
    int b = blockIdx.x;
    if (b < 100) {
        float acc = 0.f;
        #pragma unroll 8
        for (int i = 0; i < HID; i++)
            acc += embed_tab[b * HID + i] * W_comb[i * HID + j];
        g_EW[b * HID + j] = acc;
    } else {
        float a0 = 0.f, a1 = 0.f, a2 = 0.f, ab = 0.f;
        #pragma unroll 8
        for (int i = 0; i < HID; i++) {
            float w = W_comb[(HID + i) * HID + j];
            a0 += W_pos[i] * w;
            a1 += W_pos[HID + i] * w;
            a2 += W_pos[2 * HID + i] * w;
            ab += b_pos[i] * w;
        }
        g_Wpc[j]           = a0;
        g_Wpc[HID + j]     = a1;
        g_Wpc[2 * HID + j] = a2;
        g_Wpc[3 * HID + j] = ab + b_comb[j];
    }
}

// ---------------- weight split: Bt_hi/lo[n*HID+k] = split(W[k*HID+n]) ----------
__global__ void wprep_kernel(const float* __restrict__ W1all, const float* __restrict__ W2all) {
    int mat = blockIdx.x;
    const float* W = ((mat & 1) ? W2all : W1all) + (size_t)(mat >> 1) * HID * HID;
    __nv_bfloat16* hi = g_whi + (size_t)mat * HID * HID;
    __nv_bfloat16* lo = g_wlo + (size_t)mat * HID * HID;
    int n = threadIdx.x;
    for (int k = 0; k < HID; k++) {
        float w = W[k * HID + n];
        __nv_bfloat16 h = __float2bfloat16(w);
        hi[n * HID + k] = h;
        lo[n * HID + k] = __float2bfloat16(w - __bfloat162float(h));
    }
}

// ---------------- x0 ------------------------------------------------------------
__global__ void x0_kernel(const int* __restrict__ z, const float* __restrict__ pos, int N) {
    int tid = blockIdx.x * blockDim.x + threadIdx.x;
    int n = tid >> 5;
    if (n >= N) return;
    int c = tid & 31;
    int zz = __ldg(z + n);
    float p0 = __ldg(pos + n * 3), p1 = __ldg(pos + n * 3 + 1), p2 = __ldg(pos + n * 3 + 2);
    float4 ew = *(const float4*)(g_EW + zz * HID + c * 4);
    float4 w0 = *(const float4*)(g_Wpc + c * 4);
    float4 w1 = *(const float4*)(g_Wpc + HID + c * 4);
    float4 w2 = *(const float4*)(g_Wpc + 2 * HID + c * 4);
    float4 bf = *(const float4*)(g_Wpc + 3 * HID + c * 4);
    float4 v;
    v.x = fmaxf(ew.x + p0 * w0.x + p1 * w1.x + p2 * w2.x + bf.x, 0.f);
    v.y = fmaxf(ew.y + p0 * w0.y + p1 * w1.y + p2 * w2.y + bf.y, 0.f);
    v.z = fmaxf(ew.z + p0 * w0.z + p1 * w1.z + p2 * w2.z + bf.z, 0.f);
    v.w = fmaxf(ew.w + p0 * w0.w + p1 * w1.w + p2 * w2.w + bf.w, 0.f);
    *(float4*)(g_x + n * HID + c * 4) = v;
}

// ---------------- CSR aggregation ----------------------------------------------
__global__ void agg_kernel(int N) {
    int tid = blockIdx.x * blockDim.x + threadIdx.x;
    int n = tid >> 5;
    if (n >= N) return;
    int lane = tid & 31;
    const float4* x4 = (const float4*)g_x;
    float4 a0 = x4[n * 32 + lane];
    float4 a1 = {0.f, 0.f, 0.f, 0.f};
    float4 a2 = {0.f, 0.f, 0.f, 0.f};
    float4 a3 = {0.f, 0.f, 0.f, 0.f};
    int beg = __ldg(&g_off[n]), end = __ldg(&g_off[n + 1]);
    int e = beg;
    for (; e + 4 <= end; e += 4) {
        int s0 = __ldg(&g_srcs[e]);
        int s1 = __ldg(&g_srcs[e + 1]);
        int s2 = __ldg(&g_srcs[e + 2]);
        int s3 = __ldg(&g_srcs[e + 3]);
        float4 v0 = x4[s0 * 32 + lane];
        float4 v1 = x4[s1 * 32 + lane];
        float4 v2 = x4[s2 * 32 + lane];
        float4 v3 = x4[s3 * 32 + lane];
        a0.x += v0.x; a0.y += v0.y; a0.z += v0.z; a0.w += v0.w;
        a1.x += v1.x; a1.y += v1.y; a1.z += v1.z; a1.w += v1.w;
        a2.x += v2.x; a2.y += v2.y; a2.z += v2.z; a2.w += v2.w;
        a3.x += v3.x; a3.y += v3.y; a3.z += v3.z; a3.w += v3.w;
    }
    for (; e < end; e++) {
        int s = __ldg(&g_srcs[e]);
        float4 v = x4[s * 32 + lane];
        a0.x += v.x; a0.y += v.y; a0.z += v.z; a0.w += v.w;
    }
    float4 r;
    r.x = a0.x + a1.x + a2.x + a3.x;
    r.y = a0.y + a1.y + a2.y + a3.y;
    r.z = a0.z + a1.z + a2.z + a3.z;
    r.w = a0.w + a1.w + a2.w + a3.w;
    ((float4*)g_h)[n * 32 + lane] = r;
}

// ================= HMMA bf16x3 GEMM =============================================
// C[M,128] = act(A[M,128] @ W + bias); W as transposed bf16 hi/lo (k-contiguous).
// CTA: 128x128 tile, 8 warps (2 row x 4 col), warp tile 64x32.
// D = Ahi*Bhi + Ahi*Blo + Alo*Bhi, fp32 accum via mma.sync m16n8k16.
#define PAD 136                        // bf16 elements per smem row (272 B)
#define OFF_AHI 0
#define OFF_ALO (128 * PAD * 2)
#define OFF_BHI (2 * 128 * PAD * 2)
#define OFF_BLO (3 * 128 * PAD * 2)
#define SMEM_TC (4 * 128 * PAD * 2)    // 139264 B

__global__ __launch_bounds__(256, 1)
void gemm_tc(const float* __restrict__ A,
             const __nv_bfloat16* __restrict__ Bhi, const __nv_bfloat16* __restrict__ Blo,
             const float* __restrict__ bias, float* __restrict__ C,
             const int* __restrict__ batch, int M, int do_relu) {
    extern __shared__ char smem[];
    uint32_t sb = smem_u32(smem);
    int t = threadIdx.x, wid = t >> 5, lane = t & 31;
    int row0 = blockIdx.x * 128;
    int warp_m = wid & 1, warp_n = wid >> 1;

    // ---- stage A (f32 -> bf16 hi/lo split) ----
    #pragma unroll
    for (int i = 0; i < 8; i++) {
        int idx = i * 256 + t;             // 8-elem chunk: 2048 total
        int r = idx >> 4, k8 = idx & 15;
        int row = row0 + r;
        if (row >= M) row = M - 1;         // clamp; stores guarded later
        const float4* ap = (const float4*)(A + (size_t)row * HID + k8 * 8);
        float4 aA = ap[0], aB = ap[1];
        __nv_bfloat162 h0 = __floats2bfloat162_rn(aA.x, aA.y);
        __nv_bfloat162 h1 = __floats2bfloat162_rn(aA.z, aA.w);
        __nv_bfloat162 h2 = __floats2bfloat162_rn(aB.x, aB.y);
        __nv_bfloat162 h3 = __floats2bfloat162_rn(aB.z, aB.w);
        __nv_bfloat162 l0 = __floats2bfloat162_rn(aA.x - __bfloat162float(h0.x), aA.y - __bfloat162float(h0.y));
        __nv_bfloat162 l1 = __floats2bfloat162_rn(aA.z - __bfloat162float(h1.x), aA.w - __bfloat162float(h1.y));
        __nv_bfloat162 l2 = __floats2bfloat162_rn(aB.x - __bfloat162float(h2.x), aB.y - __bfloat162float(h2.y));
        __nv_bfloat162 l3 = __floats2bfloat162_rn(aB.z - __bfloat162float(h3.x), aB.w - __bfloat162float(h3.y));
        uint4 hv = {*(uint32_t*)&h0, *(uint32_t*)&h1, *(uint32_t*)&h2, *(uint32_t*)&h3};
        uint4 lv = {*(uint32_t*)&l0, *(uint32_t*)&l1, *(uint32_t*)&l2, *(uint32_t*)&l3};
        uint32_t off = (uint32_t)(r * PAD + k8 * 8) * 2;
        *(uint4*)(smem + OFF_AHI + off) = hv;
        *(uint4*)(smem + OFF_ALO + off) = lv;
    }
    // ---- stage B (bf16 copy) ----
    #pragma unroll
    for (int i = 0; i < 8; i++) {
        int idx = i * 256 + t;
        int n = idx >> 4, k8 = idx & 15;
        uint32_t off = (uint32_t)(n * PAD + k8 * 8) * 2;
        *(uint4*)(smem + OFF_BHI + off) = ((const uint4*)Bhi)[idx];
        *(uint4*)(smem + OFF_BLO + off) = ((const uint4*)Blo)[idx];
    }
    __syncthreads();

    // ---- ldmatrix lane base addresses ----
    // A (m16k16 tile): lanes 0-15 -> rows base+l @k0; 16-31 -> rows base+(l-16) @k0+8
    int a_r = warp_m * 64 + (lane & 15);
    int a_k = (lane >> 4) * 8;
    uint32_t aoff = (uint32_t)(a_r * PAD + a_k) * 2;
    // B (n16k16 block): n = nb*16 + (l&7) + (l>=16)*8 ; k = ((l>>3)&1)*8
    int b_n = warp_n * 32 + (lane & 7) + ((lane >> 4) << 3);
    int b_k = ((lane >> 3) & 1) * 8;
    uint32_t boff = (uint32_t)(b_n * PAD + b_k) * 2;

    float acc[4][4][4];
    #pragma unroll
    for (int i = 0; i < 4; i++)
        #pragma unroll
        for (int j = 0; j < 4; j++)
            acc[i][j][0] = acc[i][j][1] = acc[i][j][2] = acc[i][j][3] = 0.f;

    #pragma unroll
    for (int ks = 0; ks < 8; ks++) {
        uint32_t kb = (uint32_t)(ks * 16) * 2;     // byte advance along k
        uint32_t ah[4][4], al[4][4], bh[2][4], bl[2][4];
        #pragma unroll
        for (int mt = 0; mt < 4; mt++) {
            uint32_t ad = sb + aoff + (uint32_t)(mt * 16 * PAD) * 2 + kb;
            LDSM_X4(ah[mt][0], ah[mt][1], ah[mt][2], ah[mt][3], ad + OFF_AHI);
            LDSM_X4(al[mt][0], al[mt][1], al[mt][2], al[mt][3], ad + OFF_ALO);
        }
        #pragma unroll
        for (int nb = 0; nb < 2; nb++) {
            uint32_t bd = sb + boff + (uint32_t)(nb * 16 * PAD) * 2 + kb;
            LDSM_X4(bh[nb][0], bh[nb][1], bh[nb][2], bh[nb][3], bd + OFF_BHI);
            LDSM_X4(bl[nb][0], bl[nb][1], bl[nb][2], bl[nb][3], bd + OFF_BLO);
        }
        #pragma unroll
        for (int mt = 0; mt < 4; mt++) {
            #pragma unroll
            for (int nt = 0; nt < 4; nt++) {
                int nb = nt >> 1, h = (nt & 1) * 2;
                MMA16816(acc[mt][nt], ah[mt], bh[nb][h], bh[nb][h + 1]);
                MMA16816(acc[mt][nt], ah[mt], bl[nb][h], bl[nb][h + 1]);
                MMA16816(acc[mt][nt], al[mt], bh[nb][h], bh[nb][h + 1]);
            }
        }
    }

    // ---- epilogue: c0,c1 -> row g cols 2t,2t+1 ; c2,c3 -> row g+8 ----
    int g = lane >> 2, tq = lane & 3;
    #pragma unroll
    for (int mt = 0; mt < 4; mt++) {
        int rbase = row0 + warp_m * 64 + mt * 16 + g;
        #pragma unroll
        for (int nt = 0; nt < 4; nt++) {
            int col = warp_n * 32 + nt * 8 + tq * 2;
            float bx = __ldg(bias + col), by = __ldg(bias + col + 1);
            float v0 = acc[mt][nt][0] + bx, v1 = acc[mt][nt][1] + by;
            float v2 = acc[mt][nt][2] + bx, v3 = acc[mt][nt][3] + by;
            if (do_relu) {
                v0 = fmaxf(v0, 0.f); v1 = fmaxf(v1, 0.f);
                v2 = fmaxf(v2, 0.f); v3 = fmaxf(v3, 0.f);
            }
            if (rbase < M) {
                *(float2*)(C + (size_t)rbase * HID + col) = make_float2(v0, v1);
                if (batch) red_add_v2(g_pool + __ldg(batch + rbase) * HID + col, v0, v1);
            }
            if (rbase + 8 < M) {
                *(float2*)(C + (size_t)(rbase + 8) * HID + col) = make_float2(v2, v3);
                if (batch) red_add_v2(g_pool + __ldg(batch + rbase + 8) * HID + col, v2, v3);
            }
        }
    }
}

// ---------------- pooling prep --------------------------------------------------
__global__ void zero_pool_kernel() {
    int tid = blockIdx.x * blockDim.x + threadIdx.x;
    if (tid < NG * HID) g_pool[tid] = 0.f;
}

// ---------------- heads ---------------------------------------------------------
__global__ void heads_kernel(const float* __restrict__ W1, const float* __restrict__ b1,
                             const float* __restrict__ W2, const float* __restrict__ b2,
                             float* __restrict__ out) {
    __shared__ float sa[HID];
    __shared__ float red[HID];
    __shared__ float o[4];
    int g = blockIdx.x, j = threadIdx.x;
    sa[j] = g_pool[g * HID + j];
    __syncthreads();
    for (int k = 0; k < 4; k++) {
        float acc = b1[k * HID + j];
        const float* w = W1 + k * HID * HID + j;
        #pragma unroll 8
        for (int i = 0; i < HID; i++) acc += sa[i] * w[i * HID];
        acc = fmaxf(acc, 0.f);
        red[j] = acc * W2[k * HID + j];
        __syncthreads();
        for (int s = 64; s > 0; s >>= 1) {
            if (j < s) red[j] += red[j + s];
            __syncthreads();
        }
        if (j == 0) o[k] = red[0] + b2[k];
        __syncthreads();
    }
    if (j == 0) {
        float alpha = fmaxf(softplusf(o[0]) + 1.f, 1.f + 1e-4f);
        float beta  = softplusf(o[1]);
        float nu    = softplusf(o[2]);
        float gamma = o[3];
        float am1 = alpha - 1.f;
        out[g]            = gamma;
        out[NG + g]       = beta / am1;
        out[2 * NG + g]   = beta / (am1 * nu);
        out[3 * NG + g]   = nu;
        out[4 * NG + g]   = alpha;
        out[5 * NG + g]   = beta;
    }
}

// ---------------- driver --------------------------------------------------------
extern "C" void kernel_launch(void* const* d_in, const int* in_sizes, int n_in,
                              void* d_out, int out_size) {
    const int*   z        = (const int*)d_in[0];
    const float* pos      = (const float*)d_in[1];
    const int*   batch    = (const int*)d_in[2];
    const int*   eidx     = (const int*)d_in[3];
    const float* embed    = (const float*)d_in[4];
    const float* W_pos    = (const float*)d_in[5];
    const float* b_pos    = (const float*)d_in[6];
    const float* W_comb   = (const float*)d_in[7];
    const float* b_comb   = (const float*)d_in[8];
    const float* gin_W1   = (const float*)d_in[9];
    const float* gin_b1   = (const float*)d_in[10];
    const float* gin_W2   = (const float*)d_in[11];
    const float* gin_b2   = (const float*)d_in[12];
    const float* head_W1  = (const float*)d_in[13];
    const float* head_b1  = (const float*)d_in[14];
    const float* head_W2  = (const float*)d_in[15];
    const float* head_b2  = (const float*)d_in[16];
    float* out = (float*)d_out;

    const int N = in_sizes[0];
    const int E = in_sizes[3] / 2;
    const int* src = eidx;
    const int* dst = eidx + E;

    float *x, *h, *tmp;
    __nv_bfloat16 *whi, *wlo;
    cudaGetSymbolAddress((void**)&x, g_x);
    cudaGetSymbolAddress((void**)&h, g_h);
    cudaGetSymbolAddress((void**)&tmp, g_tmp);
    cudaGetSymbolAddress((void**)&whi, g_whi);
    cudaGetSymbolAddress((void**)&wlo, g_wlo);

    cudaFuncSetAttribute(gemm_tc, cudaFuncAttributeMaxDynamicSharedMemorySize, SMEM_TC);

    // 1. CSR build + weight folding/splitting + pool zero
    zero_deg_kernel<<<(NN + 255) / 256, 256>>>();
    hist_kernel<<<(E + 255) / 256, 256>>>(dst, E);
    scan_kernel<<<1, 1024>>>();
    fill_kernel<<<(E + 255) / 256, 256>>>(src, dst, E);
    prep_kernel<<<101, 128>>>(embed, W_pos, b_pos, W_comb, b_comb);
    wprep_kernel<<<8, 128>>>(gin_W1, gin_W2);
    zero_pool_kernel<<<(NG * HID + 255) / 256, 256>>>();

    // 2. x0
    x0_kernel<<<(N * 32 + 255) / 256, 256>>>(z, pos, N);

    // 3. GIN layers (HMMA bf16x3 GEMMs)
    const int gblocks = (N + 127) / 128;
    const int agg_blocks = (N * 32 + 255) / 256;
    for (int l = 0; l < 4; l++) {
        agg_kernel<<<agg_blocks, 256>>>(N);
        size_t m1 = (size_t)(2 * l) * HID * HID;
        size_t m2 = (size_t)(2 * l + 1) * HID * HID;
        gemm_tc<<<gblocks, 256, SMEM_TC>>>(h, whi + m1, wlo + m1,
                                           gin_b1 + l * HID, tmp, nullptr, N, 1);
        const int* bptr = (l == 3) ? batch : nullptr;
        int relu = (l < 3) ? 1 : 0;
        gemm_tc<<<gblocks, 256, SMEM_TC>>>(tmp, whi + m2, wlo + m2,
                                           gin_b2 + l * HID, x, bptr, N, relu);
    }

    // 4. heads
    heads_kernel<<<NG, 128>>>(head_W1, head_b1, head_W2, head_b2, out);
}

// round 6
// speedup vs baseline: 2.6270x; 1.0566x over previous
#include <cuda_runtime.h>
#include <cuda_bf16.h>
#include <math.h>
#include <stdint.h>

#define NN 50000
#define NE_MAX 800000
#define HID 128
#define NG 512

// ---------------- scratch (static __device__, no runtime alloc) ----------------
__device__ float g_x[NN * HID];
__device__ float g_h[NN * HID];
__device__ float g_tmp[NN * HID];
__device__ float g_pool[NG * HID];
__device__ float g_EW[100 * HID];
__device__ float g_Wpc[4 * HID];
__device__ int   g_deg[NN];
__device__ int   g_off[NN + 1];
__device__ int   g_cur[NN];
__device__ int   g_srcs[NE_MAX];
// bf16 hi/lo split, TRANSPOSED weights: Bt[n*HID+k] = W[k*HID+n]; 8 matrices
__device__ __nv_bfloat16 g_whi[8 * HID * HID];
__device__ __nv_bfloat16 g_wlo[8 * HID * HID];

__device__ __forceinline__ float softplusf(float x) {
    return fmaxf(x, 0.f) + log1pf(expf(-fabsf(x)));
}

__device__ __forceinline__ void red_add_v2(float* p, float a, float b) {
    asm volatile("red.global.add.v2.f32 [%0], {%1, %2};"
                 :: "l"(p), "f"(a), "f"(b) : "memory");
}

__device__ __forceinline__ uint32_t smem_u32(const void* p) {
    uint32_t a;
    asm("{ .reg .u64 t; cvta.to.shared.u64 t, %1; cvt.u32.u64 %0, t; }" : "=r"(a) : "l"(p));
    return a;
}

#define LDSM_X4(r0, r1, r2, r3, addr) \
    asm volatile("ldmatrix.sync.aligned.m8n8.x4.shared.b16 {%0,%1,%2,%3}, [%4];" \
                 : "=r"(r0), "=r"(r1), "=r"(r2), "=r"(r3) : "r"(addr))

#define MMA16816(c, a, b0, b1) \
    asm volatile("mma.sync.aligned.m16n8k16.row.col.f32.bf16.bf16.f32 " \
                 "{%0,%1,%2,%3}, {%4,%5,%6,%7}, {%8,%9}, {%0,%1,%2,%3};" \
                 : "+f"((c)[0]), "+f"((c)[1]), "+f"((c)[2]), "+f"((c)[3]) \
                 : "r"((a)[0]), "r"((a)[1]), "r"((a)[2]), "r"((a)[3]), "r"(b0), "r"(b1))

#define CP_ASYNC16(dst, src) \
    asm volatile("cp.async.ca.shared.global [%0], [%1], 16;" :: "r"(dst), "l"(src))
#define CP_COMMIT() asm volatile("cp.async.commit_group;" ::: "memory")
#define CP_WAIT0()  asm volatile("cp.async.wait_group 0;" ::: "memory")

// ================= CSR build ====================================================
// zero g_deg + g_pool in one kernel
__global__ void zero_kernel() {
    int i = blockIdx.x * blockDim.x + threadIdx.x;
    if (i < NN) g_deg[i] = 0;
    if (i < NG * HID) g_pool[i] = 0.f;
}

// 4 edges per thread; atomicAdd result unused -> REDG
__global__ void hist_kernel(const int* __restrict__ dst, int E) {
    int i = blockIdx.x * blockDim.x + threadIdx.x;
    int e = i * 4;
    if (e + 3 < E) {
        int4 d = ((const int4*)dst)[i];
        atomicAdd(&g_deg[d.x], 1);
        atomicAdd(&g_deg[d.y], 1);
        atomicAdd(&g_deg[d.z], 1);
        atomicAdd(&g_deg[d.w], 1);
    } else {
        for (; e < E; e++) atomicAdd(&g_deg[__ldg(dst + e)], 1);
    }
}

__global__ void scan_kernel() {
    __shared__ int part[1024];
    int t = threadIdx.x;
    const int CH = (NN + 1023) / 1024;
    int base = t * CH;
    int s = 0;
    #pragma unroll 8
    for (int i = 0; i < CH; i++) { int idx = base + i; if (idx < NN) s += g_deg[idx]; }
    part[t] = s;
    __syncthreads();
    for (int off = 1; off < 1024; off <<= 1) {
        int v = (t >= off) ? part[t - off] : 0;
        __syncthreads();
        part[t] += v;
        __syncthreads();
    }
    int run = (t == 0) ? 0 : part[t - 1];
    #pragma unroll 8
    for (int i = 0; i < CH; i++) {
        int idx = base + i;
        if (idx < NN) { g_off[idx] = run; g_cur[idx] = run; run += g_deg[idx]; }
    }
    if (t == 1023) g_off[NN] = run;
}

// 4 edges per thread; 4 independent ATOMGs in flight
__global__ void fill_kernel(const int* __restrict__ src, const int* __restrict__ dst, int E) {
    int i = blockIdx.x * blockDim.x + threadIdx.x;
    int e = i * 4;
    if (e + 3 < E) {
        int4 s = ((const int4*)src)[i];
        int4 d = ((const int4*)dst)[i];
        int p0 = atomicAdd(&g_cur[d.x], 1);
        int p1 = atomicAdd(&g_cur[d.y], 1);
        int p2 = atomicAdd(&g_cur[d.z], 1);
        int p3 = atomicAdd(&g_cur[d.w], 1);
        g_srcs[p0] = s.x;
        g_srcs[p1] = s.y;
        g_srcs[p2] = s.z;
        g_srcs[p3] = s.w;
    } else {
        for (; e < E; e++) {
            int p = atomicAdd(&g_cur[__ldg(dst + e)], 1);
            g_srcs[p] = __ldg(src + e);
        }
    }
}

// ---------------- prep: fold embedding algebra + split/transpose weights -------
__global__ void prep_kernel(const float* __restrict__ embed_tab,
                            const float* __restrict__ W_pos,
                            const float* __restrict__ b_pos,
                            const float* __restrict__ W_comb,
                            const float* __restrict__ b_comb,
                            const float* __restrict__ W1all,
                            const float* __restrict__ W2all) {
    int j = threadIdx.x;
    int b = blockIdx.x;
    if (b < 100) {
        float acc = 0.f;
        #pragma unroll 8
        for (int i = 0; i < HID; i++)
            acc += embed_tab[b * HID + i] * W_comb[i * HID + j];
        g_EW[b * HID + j] = acc;
    } else if (b == 100) {
        float a0 = 0.f, a1 = 0.f, a2 = 0.f, ab = 0.f;
        #pragma unroll 8
        for (int i = 0; i < HID; i++) {
            float w = W_comb[(HID + i) * HID + j];
            a0 += W_pos[i] * w;
            a1 += W_pos[HID + i] * w;
            a2 += W_pos[2 * HID + i] * w;
            ab += b_pos[i] * w;
        }
        g_Wpc[j]           = a0;
        g_Wpc[HID + j]     = a1;
        g_Wpc[2 * HID + j] = a2;
        g_Wpc[3 * HID + j] = ab + b_comb[j];
    } else {
        int mat = b - 101;             // 0..7
        const float* W = ((mat & 1) ? W2all : W1all) + (size_t)(mat >> 1) * HID * HID;
        __nv_bfloat16* hi = g_whi + (size_t)mat * HID * HID;
        __nv_bfloat16* lo = g_wlo + (size_t)mat * HID * HID;
        #pragma unroll 4
        for (int k = 0; k < HID; k++) {
            float w = W[k * HID + j];
            __nv_bfloat16 hh = __float2bfloat16(w);
            hi[j * HID + k] = hh;
            lo[j * HID + k] = __float2bfloat16(w - __bfloat162float(hh));
        }
    }
}

// ---------------- x0 ------------------------------------------------------------
__global__ void x0_kernel(const int* __restrict__ z, const float* __restrict__ pos, int N) {
    int tid = blockIdx.x * blockDim.x + threadIdx.x;
    int n = tid >> 5;
    if (n >= N) return;
    int c = tid & 31;
    int zz = __ldg(z + n);
    float p0 = __ldg(pos + n * 3), p1 = __ldg(pos + n * 3 + 1), p2 = __ldg(pos + n * 3 + 2);
    float4 ew = *(const float4*)(g_EW + zz * HID + c * 4);
    float4 w0 = *(const float4*)(g_Wpc + c * 4);
    float4 w1 = *(const float4*)(g_Wpc + HID + c * 4);
    float4 w2 = *(const float4*)(g_Wpc + 2 * HID + c * 4);
    float4 bf = *(const float4*)(g_Wpc + 3 * HID + c * 4);
    float4 v;
    v.x = fmaxf(ew.x + p0 * w0.x + p1 * w1.x + p2 * w2.x + bf.x, 0.f);
    v.y = fmaxf(ew.y + p0 * w0.y + p1 * w1.y + p2 * w2.y + bf.y, 0.f);
    v.z = fmaxf(ew.z + p0 * w0.z + p1 * w1.z + p2 * w2.z + bf.z, 0.f);
    v.w = fmaxf(ew.w + p0 * w0.w + p1 * w1.w + p2 * w2.w + bf.w, 0.f);
    *(float4*)(g_x + n * HID + c * 4) = v;
}

// ---------------- CSR aggregation (8-deep gather unroll) -----------------------
__global__ void agg_kernel(int N) {
    int tid = blockIdx.x * blockDim.x + threadIdx.x;
    int n = tid >> 5;
    if (n >= N) return;
    int lane = tid & 31;
    const float4* x4 = (const float4*)g_x;
    float4 a0 = x4[n * 32 + lane];
    float4 a1 = {0.f, 0.f, 0.f, 0.f};
    float4 a2 = {0.f, 0.f, 0.f, 0.f};
    float4 a3 = {0.f, 0.f, 0.f, 0.f};
    int beg = __ldg(&g_off[n]), end = __ldg(&g_off[n + 1]);
    int e = beg;
    for (; e + 8 <= end; e += 8) {
        int s0 = __ldg(&g_srcs[e]);
        int s1 = __ldg(&g_srcs[e + 1]);
        int s2 = __ldg(&g_srcs[e + 2]);
        int s3 = __ldg(&g_srcs[e + 3]);
        int s4 = __ldg(&g_srcs[e + 4]);
        int s5 = __ldg(&g_srcs[e + 5]);
        int s6 = __ldg(&g_srcs[e + 6]);
        int s7 = __ldg(&g_srcs[e + 7]);
        float4 v0 = x4[s0 * 32 + lane];
        float4 v1 = x4[s1 * 32 + lane];
        float4 v2 = x4[s2 * 32 + lane];
        float4 v3 = x4[s3 * 32 + lane];
        float4 v4 = x4[s4 * 32 + lane];
        float4 v5 = x4[s5 * 32 + lane];
        float4 v6 = x4[s6 * 32 + lane];
        float4 v7 = x4[s7 * 32 + lane];
        a0.x += v0.x; a0.y += v0.y; a0.z += v0.z; a0.w += v0.w;
        a1.x += v1.x; a1.y += v1.y; a1.z += v1.z; a1.w += v1.w;
        a2.x += v2.x; a2.y += v2.y; a2.z += v2.z; a2.w += v2.w;
        a3.x += v3.x; a3.y += v3.y; a3.z += v3.z; a3.w += v3.w;
        a0.x += v4.x; a0.y += v4.y; a0.z += v4.z; a0.w += v4.w;
        a1.x += v5.x; a1.y += v5.y; a1.z += v5.z; a1.w += v5.w;
        a2.x += v6.x; a2.y += v6.y; a2.z += v6.z; a2.w += v6.w;
        a3.x += v7.x; a3.y += v7.y; a3.z += v7.z; a3.w += v7.w;
    }
    for (; e < end; e++) {
        int s = __ldg(&g_srcs[e]);
        float4 v = x4[s * 32 + lane];
        a0.x += v.x; a0.y += v.y; a0.z += v.z; a0.w += v.w;
    }
    float4 r;
    r.x = a0.x + a1.x + a2.x + a3.x;
    r.y = a0.y + a1.y + a2.y + a3.y;
    r.z = a0.z + a1.z + a2.z + a3.z;
    r.w = a0.w + a1.w + a2.w + a3.w;
    ((float4*)g_h)[n * 32 + lane] = r;
}

// ================= HMMA bf16x3 GEMM =============================================
#define PAD 136
#define OFF_AHI 0
#define OFF_ALO (128 * PAD * 2)
#define OFF_BHI (2 * 128 * PAD * 2)
#define OFF_BLO (3 * 128 * PAD * 2)
#define SMEM_TC (4 * 128 * PAD * 2)

__global__ __launch_bounds__(256, 1)
void gemm_tc(const float* __restrict__ A,
             const __nv_bfloat16* __restrict__ Bhi, const __nv_bfloat16* __restrict__ Blo,
             const float* __restrict__ bias, float* __restrict__ C,
             const int* __restrict__ batch, int M, int do_relu) {
    extern __shared__ char smem[];
    uint32_t sb = smem_u32(smem);
    int t = threadIdx.x, wid = t >> 5, lane = t & 31;
    int row0 = blockIdx.x * 128;
    int warp_m = wid & 1, warp_n = wid >> 1;

    // ---- B via cp.async (overlaps with A convert below) ----
    #pragma unroll
    for (int i = 0; i < 8; i++) {
        int idx = i * 256 + t;
        int n = idx >> 4, k8 = idx & 15;
        uint32_t off = (uint32_t)(n * PAD + k8 * 8) * 2;
        CP_ASYNC16(sb + OFF_BHI + off, (const char*)Bhi + idx * 16);
        CP_ASYNC16(sb + OFF_BLO + off, (const char*)Blo + idx * 16);
    }
    CP_COMMIT();

    // ---- A: load f32, split bf16 hi/lo, store ----
    #pragma unroll
    for (int i = 0; i < 8; i++) {
        int idx = i * 256 + t;
        int r = idx >> 4, k8 = idx & 15;
        int row = row0 + r;
        if (row >= M) row = M - 1;
        const float4* ap = (const float4*)(A + (size_t)row * HID + k8 * 8);
        float4 aA = ap[0], aB = ap[1];
        __nv_bfloat162 h0 = __floats2bfloat162_rn(aA.x, aA.y);
        __nv_bfloat162 h1 = __floats2bfloat162_rn(aA.z, aA.w);
        __nv_bfloat162 h2 = __floats2bfloat162_rn(aB.x, aB.y);
        __nv_bfloat162 h3 = __floats2bfloat162_rn(aB.z, aB.w);
        __nv_bfloat162 l0 = __floats2bfloat162_rn(aA.x - __bfloat162float(h0.x), aA.y - __bfloat162float(h0.y));
        __nv_bfloat162 l1 = __floats2bfloat162_rn(aA.z - __bfloat162float(h1.x), aA.w - __bfloat162float(h1.y));
        __nv_bfloat162 l2 = __floats2bfloat162_rn(aB.x - __bfloat162float(h2.x), aB.y - __bfloat162float(h2.y));
        __nv_bfloat162 l3 = __floats2bfloat162_rn(aB.z - __bfloat162float(h3.x), aB.w - __bfloat162float(h3.y));
        uint4 hv = {*(uint32_t*)&h0, *(uint32_t*)&h1, *(uint32_t*)&h2, *(uint32_t*)&h3};
        uint4 lv = {*(uint32_t*)&l0, *(uint32_t*)&l1, *(uint32_t*)&l2, *(uint32_t*)&l3};
        uint32_t off = (uint32_t)(r * PAD + k8 * 8) * 2;
        *(uint4*)(smem + OFF_AHI + off) = hv;
        *(uint4*)(smem + OFF_ALO + off) = lv;
    }
    CP_WAIT0();
    __syncthreads();

    int a_r = warp_m * 64 + (lane & 15);
    int a_k = (lane >> 4) * 8;
    uint32_t aoff = (uint32_t)(a_r * PAD + a_k) * 2;
    int b_n = warp_n * 32 + (lane & 7) + ((lane >> 4) << 3);
    int b_k = ((lane >> 3) & 1) * 8;
    uint32_t boff = (uint32_t)(b_n * PAD + b_k) * 2;

    float acc[4][4][4];
    #pragma unroll
    for (int i = 0; i < 4; i++)
        #pragma unroll
        for (int j = 0; j < 4; j++)
            acc[i][j][0] = acc[i][j][1] = acc[i][j][2] = acc[i][j][3] = 0.f;

    #pragma unroll
    for (int ks = 0; ks < 8; ks++) {
        uint32_t kb = (uint32_t)(ks * 16) * 2;
        uint32_t ah[4][4], al[4][4], bh[2][4], bl[2][4];
        #pragma unroll
        for (int mt = 0; mt < 4; mt++) {
            uint32_t ad = sb + aoff + (uint32_t)(mt * 16 * PAD) * 2 + kb;
            LDSM_X4(ah[mt][0], ah[mt][1], ah[mt][2], ah[mt][3], ad + OFF_AHI);
            LDSM_X4(al[mt][0], al[mt][1], al[mt][2], al[mt][3], ad + OFF_ALO);
        }
        #pragma unroll
        for (int nb = 0; nb < 2; nb++) {
            uint32_t bd = sb + boff + (uint32_t)(nb * 16 * PAD) * 2 + kb;
            LDSM_X4(bh[nb][0], bh[nb][1], bh[nb][2], bh[nb][3], bd + OFF_BHI);
            LDSM_X4(bl[nb][0], bl[nb][1], bl[nb][2], bl[nb][3], bd + OFF_BLO);
        }
        #pragma unroll
        for (int mt = 0; mt < 4; mt++) {
            #pragma unroll
            for (int nt = 0; nt < 4; nt++) {
                int nb = nt >> 1, h = (nt & 1) * 2;
                MMA16816(acc[mt][nt], ah[mt], bh[nb][h], bh[nb][h + 1]);
                MMA16816(acc[mt][nt], ah[mt], bl[nb][h], bl[nb][h + 1]);
                MMA16816(acc[mt][nt], al[mt], bh[nb][h], bh[nb][h + 1]);
            }
        }
    }

    int g = lane >> 2, tq = lane & 3;
    #pragma unroll
    for (int mt = 0; mt < 4; mt++) {
        int rbase = row0 + warp_m * 64 + mt * 16 + g;
        #pragma unroll
        for (int nt = 0; nt < 4; nt++) {
            int col = warp_n * 32 + nt * 8 + tq * 2;
            float bx = __ldg(bias + col), by = __ldg(bias + col + 1);
            float v0 = acc[mt][nt][0] + bx, v1 = acc[mt][nt][1] + by;
            float v2 = acc[mt][nt][2] + bx, v3 = acc[mt][nt][3] + by;
            if (do_relu) {
                v0 = fmaxf(v0, 0.f); v1 = fmaxf(v1, 0.f);
                v2 = fmaxf(v2, 0.f); v3 = fmaxf(v3, 0.f);
            }
            if (rbase < M) {
                *(float2*)(C + (size_t)rbase * HID + col) = make_float2(v0, v1);
                if (batch) red_add_v2(g_pool + __ldg(batch + rbase) * HID + col, v0, v1);
            }
            if (rbase + 8 < M) {
                *(float2*)(C + (size_t)(rbase + 8) * HID + col) = make_float2(v2, v3);
                if (batch) red_add_v2(g_pool + __ldg(batch + rbase + 8) * HID + col, v2, v3);
            }
        }
    }
}

// ---------------- heads ---------------------------------------------------------
__global__ void heads_kernel(const float* __restrict__ W1, const float* __restrict__ b1,
                             const float* __restrict__ W2, const float* __restrict__ b2,
                             float* __restrict__ out) {
    __shared__ float sa[HID];
    __shared__ float red[HID];
    __shared__ float o[4];
    int g = blockIdx.x, j = threadIdx.x;
    sa[j] = g_pool[g * HID + j];
    __syncthreads();
    for (int k = 0; k < 4; k++) {
        float acc = b1[k * HID + j];
        const float* w = W1 + k * HID * HID + j;
        #pragma unroll 8
        for (int i = 0; i < HID; i++) acc += sa[i] * w[i * HID];
        acc = fmaxf(acc, 0.f);
        red[j] = acc * W2[k * HID + j];
        __syncthreads();
        for (int s = 64; s > 0; s >>= 1) {
            if (j < s) red[j] += red[j + s];
            __syncthreads();
        }
        if (j == 0) o[k] = red[0] + b2[k];
        __syncthreads();
    }
    if (j == 0) {
        float alpha = fmaxf(softplusf(o[0]) + 1.f, 1.f + 1e-4f);
        float beta  = softplusf(o[1]);
        float nu    = softplusf(o[2]);
        float gamma = o[3];
        float am1 = alpha - 1.f;
        out[g]            = gamma;
        out[NG + g]       = beta / am1;
        out[2 * NG + g]   = beta / (am1 * nu);
        out[3 * NG + g]   = nu;
        out[4 * NG + g]   = alpha;
        out[5 * NG + g]   = beta;
    }
}

// ---------------- driver --------------------------------------------------------
extern "C" void kernel_launch(void* const* d_in, const int* in_sizes, int n_in,
                              void* d_out, int out_size) {
    const int*   z        = (const int*)d_in[0];
    const float* pos      = (const float*)d_in[1];
    const int*   batch    = (const int*)d_in[2];
    const int*   eidx     = (const int*)d_in[3];
    const float* embed    = (const float*)d_in[4];
    const float* W_pos    = (const float*)d_in[5];
    const float* b_pos    = (const float*)d_in[6];
    const float* W_comb   = (const float*)d_in[7];
    const float* b_comb   = (const float*)d_in[8];
    const float* gin_W1   = (const float*)d_in[9];
    const float* gin_b1   = (const float*)d_in[10];
    const float* gin_W2   = (const float*)d_in[11];
    const float* gin_b2   = (const float*)d_in[12];
    const float* head_W1  = (const float*)d_in[13];
    const float* head_b1  = (const float*)d_in[14];
    const float* head_W2  = (const float*)d_in[15];
    const float* head_b2  = (const float*)d_in[16];
    float* out = (float*)d_out;

    const int N = in_sizes[0];
    const int E = in_sizes[3] / 2;
    const int* src = eidx;
    const int* dst = eidx + E;

    float *x, *h, *tmp;
    __nv_bfloat16 *whi, *wlo;
    cudaGetSymbolAddress((void**)&x, g_x);
    cudaGetSymbolAddress((void**)&h, g_h);
    cudaGetSymbolAddress((void**)&tmp, g_tmp);
    cudaGetSymbolAddress((void**)&whi, g_whi);
    cudaGetSymbolAddress((void**)&wlo, g_wlo);

    cudaFuncSetAttribute(gemm_tc, cudaFuncAttributeMaxDynamicSharedMemorySize, SMEM_TC);

    // 1. zeros + CSR build + weight prep
    const int zmax = (NG * HID > NN) ? NG * HID : NN;
    zero_kernel<<<(zmax + 255) / 256, 256>>>();
    hist_kernel<<<((E + 3) / 4 + 255) / 256, 256>>>(dst, E);
    scan_kernel<<<1, 1024>>>();
    fill_kernel<<<((E + 3) / 4 + 255) / 256, 256>>>(src, dst, E);
    prep_kernel<<<109, 128>>>(embed, W_pos, b_pos, W_comb, b_comb, gin_W1, gin_W2);

    // 2. x0
    x0_kernel<<<(N * 32 + 255) / 256, 256>>>(z, pos, N);

    // 3. GIN layers
    const int gblocks = (N + 127) / 128;
    const int agg_blocks = (N * 32 + 255) / 256;
    for (int l = 0; l < 4; l++) {
        agg_kernel<<<agg_blocks, 256>>>(N);
        size_t m1 = (size_t)(2 * l) * HID * HID;
        size_t m2 = (size_t)(2 * l + 1) * HID * HID;
        gemm_tc<<<gblocks, 256, SMEM_TC>>>(h, whi + m1, wlo + m1,
                                           gin_b1 + l * HID, tmp, nullptr, N, 1);
        const int* bptr = (l == 3) ? batch : nullptr;
        int relu = (l < 3) ? 1 : 0;
        gemm_tc<<<gblocks, 256, SMEM_TC>>>(tmp, whi + m2, wlo + m2,
                                           gin_b2 + l * HID, x, bptr, N, relu);
    }

    // 4. heads
    heads_kernel<<<NG, 128>>>(head_W1, head_b1, head_W2, head_b2, out);
}